// round 2
// baseline (speedup 1.0000x reference)
#include <cuda_runtime.h>
#include <math.h>

#define BN 65536
#define NDIM 32
#define HF 25
#define HV 128
#define KV 8
#define TB 32
#define THREADS 256
#define BETA 0.99f
#define TOLR 1e-4f
#define EPSV 1e-3f
#define MAX_ITER_R 1000

__device__ float g_h0[KV];

__device__ __forceinline__ float softplusf(float x){
  return fmaxf(x, 0.f) + log1pf(expf(-fabsf(x)));
}
__device__ __forceinline__ float sigmoidf_(float x){
  float e = expf(-fabsf(x));
  float s = 1.f / (1.f + e);
  return (x >= 0.f) ? s : (1.f - s);
}
__device__ __forceinline__ float signf_(float v){
  return (v > 0.f) ? 1.f : ((v < 0.f) ? -1.f : 0.f);
}

struct __align__(16) Smem {
  // All float4-accessed arrays explicitly 16B aligned.
  alignas(16) float W1v[NDIM*HV];    // 16KB
  alignas(16) float W2v[HV*HV];      // 64KB
  alignas(16) float W3v[HV*KV];      // 4KB
  alignas(16) float bufA[2*TB][HV];  // 32KB
  alignas(16) float bufB[2*TB][HV];  // 32KB
  alignas(16) float Hout[2*TB][KV];
  // scalar-accessed arrays (alignment-insensitive)
  float b1v[HV], b2v[HV], b3v[KV];
  float W1f[NDIM*HF], W2f[HF*HF], W3f[HF*NDIM];
  float b1f[HF], b2f[HF], b3f[NDIM];
  float X[TB][NDIM+1];
  float F[TB][NDIM+1];
  float Z[2*TB][NDIM+1];
  float h0s[KV];
  float gamma[TB], e1[TB], e2[TB], s1a[TB], s2a[TB], targ[TB];
  float Vg[TB], dVg[TB];
  int   m[TB], viol[TB], bis[TB];
  int   flags[2];
};

// C[64][HV] = A[64][LDA(K cols used)] @ W[K][HV], register tile 8 rows x 4 cols.
template<int K, int LDA>
__device__ __forceinline__ void gemm64(const float* __restrict__ A,
                                       const float* __restrict__ W,
                                       float* __restrict__ C, int tid){
  const int cg = tid & 31;
  const int rg = tid >> 5;
  const int c0 = 4 * cg;
  const int r0 = 8 * rg;
  float acc[8][4];
  #pragma unroll
  for (int u = 0; u < 8; u++)
    #pragma unroll
    for (int v = 0; v < 4; v++) acc[u][v] = 0.f;

  #pragma unroll 8
  for (int k = 0; k < K; k++){
    float4 w = *reinterpret_cast<const float4*>(&W[k*HV + c0]);
    #pragma unroll
    for (int u = 0; u < 8; u++){
      float a = A[(r0+u)*LDA + k];
      acc[u][0] = fmaf(a, w.x, acc[u][0]);
      acc[u][1] = fmaf(a, w.y, acc[u][1]);
      acc[u][2] = fmaf(a, w.z, acc[u][2]);
      acc[u][3] = fmaf(a, w.w, acc[u][3]);
    }
  }
  #pragma unroll
  for (int u = 0; u < 8; u++){
    *reinterpret_cast<float4*>(&C[(r0+u)*HV + c0]) =
        make_float4(acc[u][0], acc[u][1], acc[u][2], acc[u][3]);
  }
}

// Evaluates V-MLP over S.Z (rows 0..2TB). tangent=true: rows [TB,2TB) are JVP
// tangents of rows [0,TB). tangent=false: all rows primal; Vg[s]=V(row s),
// dVg[s]=V(row TB+s).
__device__ void eval_V(Smem& S, int tid, bool tangent){
  // ---- L1: Z @ W1v ----
  gemm64<NDIM, NDIM+1>(&S.Z[0][0], S.W1v, &S.bufB[0][0], tid);
  __syncthreads();
  if (tangent){
    for (int e = tid; e < TB*HV; e += THREADS){
      int s = e >> 7, j = e & (HV-1);
      float p = S.bufB[s][j] + S.b1v[j];
      float t = S.bufB[s+TB][j];
      S.bufA[s][j]    = softplusf(p);
      S.bufA[s+TB][j] = sigmoidf_(p) * t;
    }
  } else {
    for (int e = tid; e < 2*TB*HV; e += THREADS){
      int j = e & (HV-1);
      (&S.bufA[0][0])[e] = softplusf((&S.bufB[0][0])[e] + S.b1v[j]);
    }
  }
  __syncthreads();
  // ---- L2: bufA @ W2v ----
  gemm64<HV, HV>(&S.bufA[0][0], S.W2v, &S.bufB[0][0], tid);
  __syncthreads();
  if (tangent){
    for (int e = tid; e < TB*HV; e += THREADS){
      int s = e >> 7, j = e & (HV-1);
      float p = S.bufB[s][j] + S.b2v[j];
      float t = S.bufB[s+TB][j];
      S.bufA[s][j]    = softplusf(p);
      S.bufA[s+TB][j] = sigmoidf_(p) * t;
    }
  } else {
    for (int e = tid; e < 2*TB*HV; e += THREADS){
      int j = e & (HV-1);
      (&S.bufA[0][0])[e] = softplusf((&S.bufB[0][0])[e] + S.b2v[j]);
    }
  }
  __syncthreads();
  // ---- L3: bufA @ W3v (+b3 for primal rows) ----
  for (int o = tid; o < 2*TB*KV; o += THREADS){
    int r = o >> 3, k = o & (KV-1);
    bool prim = (!tangent) || (r < TB);
    float acc = prim ? S.b3v[k] : 0.f;
    #pragma unroll 8
    for (int i = 0; i < HV; i++) acc = fmaf(S.bufA[r][i], S.W3v[i*KV + k], acc);
    S.Hout[r][k] = acc;
  }
  __syncthreads();
  // ---- V reduction ----
  if (tid < TB){
    int s = tid;
    float zz = 0.f;
    #pragma unroll
    for (int i = 0; i < NDIM; i++){ float z = S.Z[s][i]; zz = fmaf(z, z, zz); }
    float vsum = EPSV * zz;
    if (tangent){
      float zdz = 0.f;
      #pragma unroll
      for (int i = 0; i < NDIM; i++) zdz = fmaf(S.Z[s][i], S.Z[s+TB][i], zdz);
      float dsum = 2.f * EPSV * zdz;
      #pragma unroll
      for (int k = 0; k < KV; k++){
        float d = S.Hout[s][k] - S.h0s[k];
        vsum = fmaf(d, d, vsum);
        dsum = fmaf(2.f*d, S.Hout[s+TB][k], dsum);
      }
      S.Vg[s] = vsum; S.dVg[s] = dsum;
    } else {
      #pragma unroll
      for (int k = 0; k < KV; k++){ float d = S.Hout[s][k] - S.h0s[k]; vsum = fmaf(d, d, vsum); }
      S.Vg[s] = vsum;
      float zz2 = 0.f;
      #pragma unroll
      for (int i = 0; i < NDIM; i++){ float z = S.Z[s+TB][i]; zz2 = fmaf(z, z, zz2); }
      float vs2 = EPSV * zz2;
      #pragma unroll
      for (int k = 0; k < KV; k++){ float d = S.Hout[s+TB][k] - S.h0s[k]; vs2 = fmaf(d, d, vs2); }
      S.dVg[s] = vs2;  // V of second-half rows
    }
  }
  __syncthreads();
}

__global__ void h0_kernel(const float* __restrict__ vW1, const float* __restrict__ vb1,
                          const float* __restrict__ vW2, const float* __restrict__ vb2,
                          const float* __restrict__ vW3, const float* __restrict__ vb3){
  __shared__ float h1[HV], h2[HV];
  int t = threadIdx.x;
  if (t < HV) h1[t] = softplusf(vb1[t]);     // input = 0
  __syncthreads();
  if (t < HV){
    float acc = vb2[t];
    for (int i = 0; i < HV; i++) acc = fmaf(h1[i], vW2[i*HV + t], acc);
    h2[t] = softplusf(acc);
  }
  __syncthreads();
  if (t < KV){
    float acc = vb3[t];
    for (int i = 0; i < HV; i++) acc = fmaf(h2[i], vW3[i*KV + t], acc);
    g_h0[t] = acc;
  }
}

__global__ void __launch_bounds__(THREADS, 1)
dyn_kernel(const float* __restrict__ x,
           const float* __restrict__ fW1, const float* __restrict__ fb1,
           const float* __restrict__ fW2, const float* __restrict__ fb2,
           const float* __restrict__ fW3, const float* __restrict__ fb3,
           const float* __restrict__ vW1, const float* __restrict__ vb1,
           const float* __restrict__ vW2, const float* __restrict__ vb2,
           const float* __restrict__ vW3, const float* __restrict__ vb3,
           float* __restrict__ out){
  extern __shared__ char smem_raw[];
  Smem& S = *reinterpret_cast<Smem*>(smem_raw);
  const int tid = threadIdx.x;
  const int base = blockIdx.x * TB;

  // ---- load weights + x tile ----
  for (int i = tid; i < NDIM*HV; i += THREADS) S.W1v[i] = vW1[i];
  for (int i = tid; i < HV*HV;  i += THREADS) S.W2v[i] = vW2[i];
  for (int i = tid; i < HV*KV;  i += THREADS) S.W3v[i] = vW3[i];
  for (int i = tid; i < HV;     i += THREADS){ S.b1v[i] = vb1[i]; S.b2v[i] = vb2[i]; }
  if (tid < KV)   S.b3v[tid] = vb3[tid];
  for (int i = tid; i < NDIM*HF; i += THREADS) S.W1f[i] = fW1[i];
  for (int i = tid; i < HF*HF;   i += THREADS) S.W2f[i] = fW2[i];
  for (int i = tid; i < HF*NDIM; i += THREADS) S.W3f[i] = fW3[i];
  if (tid < HF){ S.b1f[tid] = fb1[tid]; S.b2f[tid] = fb2[tid]; }
  if (tid < NDIM) S.b3f[tid] = fb3[tid];
  if (tid < KV)   S.h0s[tid] = g_h0[tid];
  for (int e = tid; e < TB*NDIM; e += THREADS){
    int s = e >> 5, i = e & 31;
    S.X[s][i] = x[(size_t)(base + s)*NDIM + i];
  }
  __syncthreads();

  // ---- fhat: 32 -> 25 -> 25 -> 32 ----
  for (int o = tid; o < TB*HF; o += THREADS){
    int s = o / HF, j = o % HF;
    float acc = S.b1f[j];
    #pragma unroll
    for (int i = 0; i < NDIM; i++) acc = fmaf(S.X[s][i], S.W1f[i*HF + j], acc);
    S.bufA[s][j] = softplusf(acc);
  }
  __syncthreads();
  for (int o = tid; o < TB*HF; o += THREADS){
    int s = o / HF, j = o % HF;
    float acc = S.b2f[j];
    #pragma unroll
    for (int i = 0; i < HF; i++) acc = fmaf(S.bufA[s][i], S.W2f[i*HF + j], acc);
    S.bufB[s][j] = softplusf(acc);
  }
  __syncthreads();
  for (int o = tid; o < TB*NDIM; o += THREADS){
    int s = o >> 5, j = o & 31;
    float acc = S.b3f[j];
    #pragma unroll
    for (int i = 0; i < HF; i++) acc = fmaf(S.bufB[s][i], S.W3f[i*NDIM + j], acc);
    S.F[s][j] = acc;
  }
  __syncthreads();

  // ---- initial eval: rows [0,TB)=x, rows [TB,2TB)=fhatx (primal) ----
  for (int e = tid; e < TB*NDIM; e += THREADS){
    int s = e >> 5, i = e & 31;
    S.Z[s][i]    = S.X[s][i];
    S.Z[TB+s][i] = S.F[s][i];
  }
  __syncthreads();
  eval_V(S, tid, false);

  if (tid < TB){
    float Vx = S.Vg[tid], Vf = S.dVg[tid];
    float tg = BETA * Vx;
    S.targ[tid] = tg;
    float r0 = Vf - tg;
    int act = (r0 > 0.f) ? 1 : 0;
    S.m[tid] = act; S.viol[tid] = act;
    S.gamma[tid] = 1.f; S.e1[tid] = 0.f; S.e2[tid] = 1.f;
    S.s1a[tid] = signf_(-tg);
    S.s2a[tid] = signf_(r0);
  }
  __syncthreads();
  if (tid == 0){ int a = 0; for (int s = 0; s < TB; s++) a |= S.m[s]; S.flags[0] = a; }
  __syncthreads();

  // ---- Newton + bisection sweeps (replicates reference masked loop) ----
  for (int it = 0; it < MAX_ITER_R && S.flags[0]; ++it){
    for (int e = tid; e < TB*NDIM; e += THREADS){
      int s = e >> 5, i = e & 31;
      S.Z[s][i] = S.gamma[s] * S.F[s][i];
    }
    __syncthreads();
    eval_V(S, tid, true);   // Vg = V(gamma*F), dVg = dV/dgamma

    if (tid < TB){
      S.bis[tid] = 0;
      if (S.m[tid]){
        float resid = S.Vg[tid] - S.targ[tid];
        if (it > 0 && fabsf(resid) <= TOLR){
          S.m[tid] = 0;   // converged at end of previous body iteration
        } else {
          float g = S.gamma[tid] - resid / S.dVg[tid];
          float lo = S.e1[tid], hi = S.e2[tid];
          if (g < lo || g > hi || !isfinite(g)){
            S.gamma[tid] = 0.5f * (lo + hi);
            S.bis[tid] = 1;
          } else {
            S.gamma[tid] = g;
          }
        }
      }
    }
    __syncthreads();
    if (tid == 0){
      int a = 0, b = 0;
      for (int s = 0; s < TB; s++){ a |= S.m[s]; b |= S.bis[s]; }
      S.flags[0] = a; S.flags[1] = b;
    }
    __syncthreads();

    if (S.flags[1]){
      // evaluate V at bisection midpoints (primal only)
      for (int e = tid; e < TB*NDIM; e += THREADS){
        int s = e >> 5, i = e & 31;
        S.Z[s][i] = S.gamma[s] * S.F[s][i];
      }
      __syncthreads();
      eval_V(S, tid, false);
      if (tid < TB && S.bis[tid]){
        float a  = S.gamma[tid];
        float sa = signf_(S.Vg[tid] - S.targ[tid]);
        float s1 = S.s1a[tid], s2 = S.s2a[tid];
        if (sa * s1 < 0.f){ S.e2[tid] = a; S.s2a[tid] = sa; }
        if (sa * s2 < 0.f){ S.e1[tid] = a; S.s1a[tid] = sa; }
      }
      __syncthreads();
    }
  }

  // ---- output ----
  for (int e = tid; e < TB*NDIM; e += THREADS){
    int s = e >> 5, i = e & 31;
    float f = S.F[s][i];
    out[(size_t)(base + s)*NDIM + i] = S.viol[s] ? f * S.gamma[s] : f;
  }
}

extern "C" void kernel_launch(void* const* d_in, const int* in_sizes, int n_in,
                              void* d_out, int out_size){
  const float* x   = (const float*)d_in[0];
  const float* fW1 = (const float*)d_in[1];
  const float* fb1 = (const float*)d_in[2];
  const float* fW2 = (const float*)d_in[3];
  const float* fb2 = (const float*)d_in[4];
  const float* fW3 = (const float*)d_in[5];
  const float* fb3 = (const float*)d_in[6];
  const float* vW1 = (const float*)d_in[7];
  const float* vb1 = (const float*)d_in[8];
  const float* vW2 = (const float*)d_in[9];
  const float* vb2 = (const float*)d_in[10];
  const float* vW3 = (const float*)d_in[11];
  const float* vb3 = (const float*)d_in[12];
  float* out = (float*)d_out;

  cudaFuncSetAttribute(dyn_kernel, cudaFuncAttributeMaxDynamicSharedMemorySize,
                       (int)sizeof(Smem));
  h0_kernel<<<1, 128>>>(vW1, vb1, vW2, vb2, vW3, vb3);
  dyn_kernel<<<BN / TB, THREADS, sizeof(Smem)>>>(
      x, fW1, fb1, fW2, fb2, fW3, fb3,
      vW1, vb1, vW2, vb2, vW3, vb3, out);
}

// round 4
// speedup vs baseline: 1.4206x; 1.4206x over previous
#include <cuda_runtime.h>
#include <math.h>

#define BN 65536
#define NDIM 32
#define HF 25
#define HV 128
#define KV 8
#define TB 64
#define ROWS (2*TB)
#define THREADS 512
#define BETA 0.99f
#define TOLR 1e-4f
#define EPSV 1e-3f
#define MAX_ITER_R 1000

__device__ float g_h0[KV];

__device__ __forceinline__ float softplusf(float x){
  return fmaxf(x, 0.f) + log1pf(expf(-fabsf(x)));
}
__device__ __forceinline__ float signf_(float v){
  return (v > 0.f) ? 1.f : ((v < 0.f) ? -1.f : 0.f);
}

struct __align__(16) Smem {
  alignas(16) float W1v[NDIM*HV];   // 16KB
  alignas(16) float W2v[HV*HV];     // 64KB
  alignas(16) float W3v[HV*KV];     // 4KB
  alignas(16) float bufA[ROWS][HV]; // 64KB (single activation buffer)
  alignas(16) float Z[ROWS][NDIM];  // 16KB
  alignas(16) float Hout[ROWS][KV]; // 4KB
  alignas(16) float F[TB][NDIM];    // 8KB
  alignas(16) float X[TB][NDIM];    // 8KB
  alignas(16) float b1v[HV];
  alignas(16) float b2v[HV];
  alignas(16) float b3v[KV];
  alignas(16) float h0s[KV];
  alignas(16) float Vrow[ROWS];
  float W1f[NDIM*HF], W2f[HF*HF], W3f[HF*NDIM];
  float b1f[HF], b2f[HF], b3f[NDIM];
  float gammaS[TB], VgS[TB], dVgS[TB];
  int   mS[TB], violS[TB];
  int   idx[TB];
  int   nact;
};

// C[rlim][HV] = act(A[rlim][K] @ W[K][HV] + b). Single-buffer safe: full read
// phase, barrier, then write phase (C may alias A).
// TANGENT: rows (2j, 2j+1) within each thread's 8-row block are (primal,
// tangent) pairs: primal -> softplus(p), tangent -> sigmoid(p)*t (shared exp).
template<int K, int LDA, bool TANGENT>
__device__ __forceinline__ void gemmV(const float* __restrict__ A,
                                      const float* __restrict__ W,
                                      const float* __restrict__ bias,
                                      float* __restrict__ C,
                                      int tid, int rlim){
  const int c0 = (tid & 31) * 4;
  const int r0 = (tid >> 5) * 8;
  const bool act = (r0 < rlim);
  float acc[8][4];
  if (act){
    #pragma unroll
    for (int u = 0; u < 8; u++){ acc[u][0]=0.f; acc[u][1]=0.f; acc[u][2]=0.f; acc[u][3]=0.f; }
    #pragma unroll 4
    for (int k4 = 0; k4 < K; k4 += 4){
      float4 w0 = *reinterpret_cast<const float4*>(&W[(k4+0)*HV + c0]);
      float4 w1 = *reinterpret_cast<const float4*>(&W[(k4+1)*HV + c0]);
      float4 w2 = *reinterpret_cast<const float4*>(&W[(k4+2)*HV + c0]);
      float4 w3 = *reinterpret_cast<const float4*>(&W[(k4+3)*HV + c0]);
      #pragma unroll
      for (int u = 0; u < 8; u++){
        float4 a = *reinterpret_cast<const float4*>(&A[(r0+u)*LDA + k4]);
        acc[u][0] = fmaf(a.x,w0.x,fmaf(a.y,w1.x,fmaf(a.z,w2.x,fmaf(a.w,w3.x,acc[u][0]))));
        acc[u][1] = fmaf(a.x,w0.y,fmaf(a.y,w1.y,fmaf(a.z,w2.y,fmaf(a.w,w3.y,acc[u][1]))));
        acc[u][2] = fmaf(a.x,w0.z,fmaf(a.y,w1.z,fmaf(a.z,w2.z,fmaf(a.w,w3.z,acc[u][2]))));
        acc[u][3] = fmaf(a.x,w0.w,fmaf(a.y,w1.w,fmaf(a.z,w2.w,fmaf(a.w,w3.w,acc[u][3]))));
      }
    }
  }
  __syncthreads();   // all reads of A complete before writes (C may alias A)
  if (act){
    float4 bv = *reinterpret_cast<const float4*>(&bias[c0]);
    float bb[4] = {bv.x, bv.y, bv.z, bv.w};
    if (TANGENT){
      #pragma unroll
      for (int j = 0; j < 4; j++){
        float pr[4], tg[4];
        #pragma unroll
        for (int v = 0; v < 4; v++){
          float p = acc[2*j][v] + bb[v];
          float e = expf(-fabsf(p));
          pr[v] = fmaxf(p, 0.f) + log1pf(e);
          float s = 1.f / (1.f + e);
          float sg = (p >= 0.f) ? s : (1.f - s);
          tg[v] = sg * acc[2*j+1][v];
        }
        *reinterpret_cast<float4*>(&C[(r0+2*j  )*HV + c0]) = make_float4(pr[0],pr[1],pr[2],pr[3]);
        *reinterpret_cast<float4*>(&C[(r0+2*j+1)*HV + c0]) = make_float4(tg[0],tg[1],tg[2],tg[3]);
      }
    } else {
      #pragma unroll
      for (int u = 0; u < 8; u++){
        float o[4];
        #pragma unroll
        for (int v = 0; v < 4; v++) o[v] = softplusf(acc[u][v] + bb[v]);
        *reinterpret_cast<float4*>(&C[(r0+u)*HV + c0]) = make_float4(o[0],o[1],o[2],o[3]);
      }
    }
  }
  __syncthreads();
}

// L3 (HVxKV) + V reduction. 4 threads per row, shfl-reduce over the 4 lanes.
// TANGENT: thread a<nact returns vg=V(gamma*F), dvg=dV/dgamma for slot a.
// else: Vrow[r] = V(Z row r).
template<bool TANGENT>
__device__ __forceinline__ void l3_reduce(Smem& S, int tid, int rlim, int nact,
                                          float& vg_out, float& dvg_out){
  const int row  = tid >> 2;
  const int part = tid & 3;
  if (row < rlim){
    float hk[8];
    #pragma unroll
    for (int k = 0; k < 8; k++) hk[k] = 0.f;
    const int i0 = part * 32;
    #pragma unroll 2
    for (int i = i0; i < i0 + 32; i += 4){
      float4 a = *reinterpret_cast<const float4*>(&S.bufA[row][i]);
      float av[4] = {a.x, a.y, a.z, a.w};
      #pragma unroll
      for (int j = 0; j < 4; j++){
        float4 w0 = *reinterpret_cast<const float4*>(&S.W3v[(i+j)*KV]);
        float4 w1 = *reinterpret_cast<const float4*>(&S.W3v[(i+j)*KV + 4]);
        hk[0]=fmaf(av[j],w0.x,hk[0]); hk[1]=fmaf(av[j],w0.y,hk[1]);
        hk[2]=fmaf(av[j],w0.z,hk[2]); hk[3]=fmaf(av[j],w0.w,hk[3]);
        hk[4]=fmaf(av[j],w1.x,hk[4]); hk[5]=fmaf(av[j],w1.y,hk[5]);
        hk[6]=fmaf(av[j],w1.z,hk[6]); hk[7]=fmaf(av[j],w1.w,hk[7]);
      }
    }
    #pragma unroll
    for (int k = 0; k < 8; k++){
      hk[k] += __shfl_xor_sync(0xffffffffu, hk[k], 1);
      hk[k] += __shfl_xor_sync(0xffffffffu, hk[k], 2);
    }
    if (part == 0){
      const bool prim = TANGENT ? ((row & 1) == 0) : true;
      if (prim){
        #pragma unroll
        for (int k = 0; k < 8; k++) hk[k] += S.b3v[k];
      }
      *reinterpret_cast<float4*>(&S.Hout[row][0]) = make_float4(hk[0],hk[1],hk[2],hk[3]);
      *reinterpret_cast<float4*>(&S.Hout[row][4]) = make_float4(hk[4],hk[5],hk[6],hk[7]);
    }
  }
  __syncthreads();
  if (TANGENT){
    if (tid < nact){
      float zz = 0.f, zdz = 0.f;
      #pragma unroll
      for (int i = 0; i < NDIM; i += 4){
        float4 zp = *reinterpret_cast<const float4*>(&S.Z[2*tid][i]);
        float4 zt = *reinterpret_cast<const float4*>(&S.Z[2*tid+1][i]);
        zz  = fmaf(zp.x,zp.x,fmaf(zp.y,zp.y,fmaf(zp.z,zp.z,fmaf(zp.w,zp.w,zz))));
        zdz = fmaf(zp.x,zt.x,fmaf(zp.y,zt.y,fmaf(zp.z,zt.z,fmaf(zp.w,zt.w,zdz))));
      }
      float vsum = EPSV * zz;
      float dsum = 2.f * EPSV * zdz;
      #pragma unroll
      for (int k = 0; k < KV; k++){
        float d = S.Hout[2*tid][k] - S.h0s[k];
        vsum = fmaf(d, d, vsum);
        dsum = fmaf(2.f*d, S.Hout[2*tid+1][k], dsum);
      }
      vg_out = vsum; dvg_out = dsum;
    }
  } else {
    if (tid < rlim){
      float zz = 0.f;
      #pragma unroll
      for (int i = 0; i < NDIM; i += 4){
        float4 zp = *reinterpret_cast<const float4*>(&S.Z[tid][i]);
        zz = fmaf(zp.x,zp.x,fmaf(zp.y,zp.y,fmaf(zp.z,zp.z,fmaf(zp.w,zp.w,zz))));
      }
      float vsum = EPSV * zz;
      #pragma unroll
      for (int k = 0; k < KV; k++){
        float d = S.Hout[tid][k] - S.h0s[k];
        vsum = fmaf(d, d, vsum);
      }
      S.Vrow[tid] = vsum;
    }
  }
  __syncthreads();
}

__global__ void h0_kernel(const float* __restrict__ vW1, const float* __restrict__ vb1,
                          const float* __restrict__ vW2, const float* __restrict__ vb2,
                          const float* __restrict__ vW3, const float* __restrict__ vb3){
  __shared__ float h1[HV], h2[HV];
  int t = threadIdx.x;
  if (t < HV) h1[t] = softplusf(vb1[t]);
  __syncthreads();
  if (t < HV){
    float acc = vb2[t];
    for (int i = 0; i < HV; i++) acc = fmaf(h1[i], vW2[i*HV + t], acc);
    h2[t] = softplusf(acc);
  }
  __syncthreads();
  if (t < KV){
    float acc = vb3[t];
    for (int i = 0; i < HV; i++) acc = fmaf(h2[i], vW3[i*KV + t], acc);
    g_h0[t] = acc;
  }
}

__global__ void __launch_bounds__(THREADS, 1)
dyn_kernel(const float* __restrict__ x,
           const float* __restrict__ fW1, const float* __restrict__ fb1,
           const float* __restrict__ fW2, const float* __restrict__ fb2,
           const float* __restrict__ fW3, const float* __restrict__ fb3,
           const float* __restrict__ vW1, const float* __restrict__ vb1,
           const float* __restrict__ vW2, const float* __restrict__ vb2,
           const float* __restrict__ vW3, const float* __restrict__ vb3,
           float* __restrict__ out){
  extern __shared__ char smem_raw[];
  Smem& S = *reinterpret_cast<Smem*>(smem_raw);
  const int tid = threadIdx.x;
  const int base = blockIdx.x * TB;

  // ---- load weights + x tile ----
  for (int i = tid; i < NDIM*HV; i += THREADS) S.W1v[i] = vW1[i];
  for (int i = tid; i < HV*HV;  i += THREADS) S.W2v[i] = vW2[i];
  for (int i = tid; i < HV*KV;  i += THREADS) S.W3v[i] = vW3[i];
  for (int i = tid; i < HV;     i += THREADS){ S.b1v[i] = vb1[i]; S.b2v[i] = vb2[i]; }
  if (tid < KV)   S.b3v[tid] = vb3[tid];
  for (int i = tid; i < NDIM*HF; i += THREADS) S.W1f[i] = fW1[i];
  for (int i = tid; i < HF*HF;   i += THREADS) S.W2f[i] = fW2[i];
  for (int i = tid; i < HF*NDIM; i += THREADS) S.W3f[i] = fW3[i];
  if (tid < HF){ S.b1f[tid] = fb1[tid]; S.b2f[tid] = fb2[tid]; }
  if (tid < NDIM) S.b3f[tid] = fb3[tid];
  if (tid < KV)   S.h0s[tid] = g_h0[tid];
  for (int e = tid; e < TB*NDIM; e += THREADS){
    int s = e >> 5, i = e & 31;
    S.X[s][i] = x[(size_t)(base + s)*NDIM + i];
  }
  __syncthreads();

  // ---- fhat: 32 -> 25 -> 25 -> 32 (h1 in bufA[.][0..24], h2 in bufA[.][64..88]) ----
  for (int o = tid; o < TB*HF; o += THREADS){
    int s = o / HF, j = o - s*HF;
    float acc = S.b1f[j];
    #pragma unroll
    for (int i = 0; i < NDIM; i++) acc = fmaf(S.X[s][i], S.W1f[i*HF + j], acc);
    S.bufA[s][j] = softplusf(acc);
  }
  __syncthreads();
  for (int o = tid; o < TB*HF; o += THREADS){
    int s = o / HF, j = o - s*HF;
    float acc = S.b2f[j];
    #pragma unroll
    for (int i = 0; i < HF; i++) acc = fmaf(S.bufA[s][i], S.W2f[i*HF + j], acc);
    S.bufA[s][64 + j] = softplusf(acc);
  }
  __syncthreads();
  for (int o = tid; o < TB*NDIM; o += THREADS){
    int s = o >> 5, j = o & 31;
    float acc = S.b3f[j];
    #pragma unroll
    for (int i = 0; i < HF; i++) acc = fmaf(S.bufA[s][64 + i], S.W3f[i*NDIM + j], acc);
    S.F[s][j] = acc;
  }
  __syncthreads();

  // ---- initial primal eval: row 2s = x_s, row 2s+1 = fhat(x_s) ----
  for (int e = tid; e < TB*NDIM; e += THREADS){
    int s = e >> 5, i = e & 31;
    S.Z[2*s][i]   = S.X[s][i];
    S.Z[2*s+1][i] = S.F[s][i];
  }
  __syncthreads();
  {
    float d0, d1;
    gemmV<NDIM, NDIM, false>(&S.Z[0][0], S.W1v, S.b1v, &S.bufA[0][0], tid, ROWS);
    gemmV<HV,   HV,   false>(&S.bufA[0][0], S.W2v, S.b2v, &S.bufA[0][0], tid, ROWS);
    l3_reduce<false>(S, tid, ROWS, TB, d0, d1);
  }

  // ---- per-sample state (registers of thread tid<TB) ----
  float tg = 0.f, e1l = 0.f, e2l = 1.f, s1l = 0.f, s2l = 0.f, gml = 1.f;
  int mloc = 0;
  if (tid < TB){
    float Vx = S.Vrow[2*tid], Vf = S.Vrow[2*tid+1];
    tg = BETA * Vx;
    float r0v = Vf - tg;
    mloc = (r0v > 0.f) ? 1 : 0;
    s1l = signf_(-tg);
    s2l = signf_(r0v);
    S.gammaS[tid] = 1.f;
    S.mS[tid] = mloc;
    S.violS[tid] = mloc;
  }
  __syncthreads();

  // ---- Newton + bisection sweeps, compacted to active samples ----
  for (int it = 0; it < MAX_ITER_R; ++it){
    if (tid == 0){
      int n = 0;
      for (int s = 0; s < TB; s++) if (S.mS[s]) S.idx[n++] = s;
      S.nact = n;
    }
    __syncthreads();
    const int nact = S.nact;
    if (nact == 0) break;
    const int rlim = (2*nact + 7) & ~7;

    // build compacted Z: (gamma*F, F) pairs + zero padding rows
    for (int e = tid; e < nact*NDIM; e += THREADS){
      int a = e >> 5, i = e & 31;
      int s = S.idx[a];
      float f = S.F[s][i];
      S.Z[2*a][i]   = S.gammaS[s] * f;
      S.Z[2*a+1][i] = f;
    }
    for (int e = tid; e < (rlim - 2*nact)*NDIM; e += THREADS){
      S.Z[2*nact + (e >> 5)][e & 31] = 0.f;
    }
    __syncthreads();

    {
      float vg, dvg;
      gemmV<NDIM, NDIM, true>(&S.Z[0][0], S.W1v, S.b1v, &S.bufA[0][0], tid, rlim);
      gemmV<HV,   HV,   true>(&S.bufA[0][0], S.W2v, S.b2v, &S.bufA[0][0], tid, rlim);
      l3_reduce<true>(S, tid, rlim, nact, vg, dvg);
      if (tid < nact){ int s = S.idx[tid]; S.VgS[s] = vg; S.dVgS[s] = dvg; }
    }
    __syncthreads();

    int bisloc = 0;
    if (tid < TB && mloc){
      float resid = S.VgS[tid] - tg;
      if (it > 0 && fabsf(resid) <= TOLR){
        mloc = 0; S.mS[tid] = 0;
      } else {
        float g = gml - resid / S.dVgS[tid];
        if (!isfinite(g) || g < e1l || g > e2l){
          gml = 0.5f * (e1l + e2l);
          bisloc = 1;
        } else {
          gml = g;
        }
        S.gammaS[tid] = gml;
      }
    }
    int anyBis = __syncthreads_or(bisloc);

    if (anyBis){
      // primal eval at updated gammas (bisection midpoints included)
      for (int e = tid; e < nact*NDIM; e += THREADS){
        int a = e >> 5, i = e & 31;
        int s = S.idx[a];
        S.Z[2*a][i] = S.gammaS[s] * S.F[s][i];
      }
      __syncthreads();
      float d0, d1;
      gemmV<NDIM, NDIM, false>(&S.Z[0][0], S.W1v, S.b1v, &S.bufA[0][0], tid, rlim);
      gemmV<HV,   HV,   false>(&S.bufA[0][0], S.W2v, S.b2v, &S.bufA[0][0], tid, rlim);
      l3_reduce<false>(S, tid, rlim, nact, d0, d1);
      if (tid < nact){ int s = S.idx[tid]; S.VgS[s] = S.Vrow[2*tid]; }
      __syncthreads();
      if (tid < TB && bisloc){
        float sa = signf_(S.VgS[tid] - tg);
        if (sa * s1l < 0.f){ e2l = gml; s2l = sa; }
        if (sa * s2l < 0.f){ e1l = gml; s1l = sa; }
      }
      __syncthreads();
    }
  }

  // ---- output ----
  for (int e = tid; e < TB*NDIM; e += THREADS){
    int s = e >> 5, i = e & 31;
    float f = S.F[s][i];
    out[(size_t)(base + s)*NDIM + i] = S.violS[s] ? f * S.gammaS[s] : f;
  }
}

extern "C" void kernel_launch(void* const* d_in, const int* in_sizes, int n_in,
                              void* d_out, int out_size){
  const float* x   = (const float*)d_in[0];
  const float* fW1 = (const float*)d_in[1];
  const float* fb1 = (const float*)d_in[2];
  const float* fW2 = (const float*)d_in[3];
  const float* fb2 = (const float*)d_in[4];
  const float* fW3 = (const float*)d_in[5];
  const float* fb3 = (const float*)d_in[6];
  const float* vW1 = (const float*)d_in[7];
  const float* vb1 = (const float*)d_in[8];
  const float* vW2 = (const float*)d_in[9];
  const float* vb2 = (const float*)d_in[10];
  const float* vW3 = (const float*)d_in[11];
  const float* vb3 = (const float*)d_in[12];
  float* out = (float*)d_out;

  cudaFuncSetAttribute(dyn_kernel, cudaFuncAttributeMaxDynamicSharedMemorySize,
                       (int)sizeof(Smem));
  h0_kernel<<<1, 128>>>(vW1, vb1, vW2, vb2, vW3, vb3);
  dyn_kernel<<<BN / TB, THREADS, sizeof(Smem)>>>(
      x, fW1, fb1, fW2, fb2, fW3, fb3,
      vW1, vb1, vW2, vb2, vW3, vb3, out);
}

// round 5
// speedup vs baseline: 1.7279x; 1.2163x over previous
#include <cuda_runtime.h>
#include <math.h>

#define BN 65536
#define NDIM 32
#define HF 25
#define HV 128
#define KV 8
#define TB 64
#define WARPS 16
#define THREADS 512
#define BETA 0.99f
#define TOLR 1e-4f
#define EPSV 1e-3f
#define MAX_ITER_R 1000
#define FULLM 0xffffffffu

__device__ float g_h0[KV];

__device__ __forceinline__ float softplusf_(float x){
  float e = __expf(-fabsf(x));
  return fmaxf(x, 0.f) + __logf(1.f + e);
}
__device__ __forceinline__ void sp_sig(float p, float& sp, float& sg){
  float e = __expf(-fabsf(p));
  float inv = 1.f / (1.f + e);
  sp = fmaxf(p, 0.f) + __logf(1.f + e);
  sg = (p >= 0.f) ? inv : (1.f - inv);
}
__device__ __forceinline__ float signf_(float v){
  return (v > 0.f) ? 1.f : ((v < 0.f) ? -1.f : 0.f);
}

struct __align__(16) Smem {
  alignas(16) float W1v[NDIM*HV];     // 16KB
  alignas(16) float W2v[HV*HV];       // 64KB
  alignas(16) float W3v[HV*KV];       // 4KB
  alignas(16) float Aw[WARPS][8][HV]; // 64KB per-warp activation scratch
  alignas(16) float C1w[WARPS][4][HV];// 32KB cached F@W1v
  alignas(16) float Fw[WARPS][4][NDIM];
  alignas(16) float Hw[WARPS][8][KV];
  alignas(16) float X[TB][NDIM];
  alignas(16) float b1v[HV], b2v[HV];
  alignas(16) float b3v[KV], h0s[KV];
  float W1f[NDIM*HF], W2f[HF*HF], W3f[HF*NDIM];
  float b1f[HF], b2f[HF], b3f[NDIM];
};

// Per-warp L2: A[R][HV] = act(A[R][HV] @ W2 + b2). Single-buffer (read all,
// syncwarp, write). PAIRED: rows (2j,2j+1) = (primal, tangent) share the exp.
template<int R, bool PAIRED>
__device__ __forceinline__ void l2_gemm(float (* __restrict__ A)[HV],
                                        const float* __restrict__ W2,
                                        const float* __restrict__ b2,
                                        int lane){
  const int c0 = lane * 4;
  float acc[R][4];
  #pragma unroll
  for (int r = 0; r < R; r++){ acc[r][0]=0.f; acc[r][1]=0.f; acc[r][2]=0.f; acc[r][3]=0.f; }
  #pragma unroll 2
  for (int k = 0; k < HV; k += 4){
    float4 w0 = *(const float4*)&W2[(k+0)*HV + c0];
    float4 w1 = *(const float4*)&W2[(k+1)*HV + c0];
    float4 w2 = *(const float4*)&W2[(k+2)*HV + c0];
    float4 w3 = *(const float4*)&W2[(k+3)*HV + c0];
    #pragma unroll
    for (int r = 0; r < R; r++){
      float4 a = *(const float4*)&A[r][k];
      acc[r][0]=fmaf(a.x,w0.x,fmaf(a.y,w1.x,fmaf(a.z,w2.x,fmaf(a.w,w3.x,acc[r][0]))));
      acc[r][1]=fmaf(a.x,w0.y,fmaf(a.y,w1.y,fmaf(a.z,w2.y,fmaf(a.w,w3.y,acc[r][1]))));
      acc[r][2]=fmaf(a.x,w0.z,fmaf(a.y,w1.z,fmaf(a.z,w2.z,fmaf(a.w,w3.z,acc[r][2]))));
      acc[r][3]=fmaf(a.x,w0.w,fmaf(a.y,w1.w,fmaf(a.z,w2.w,fmaf(a.w,w3.w,acc[r][3]))));
    }
  }
  __syncwarp();
  float4 bv = *(const float4*)&b2[c0];
  float bb[4] = {bv.x, bv.y, bv.z, bv.w};
  if (PAIRED){
    #pragma unroll
    for (int j = 0; j < R/2; j++){
      float pr[4], tg[4];
      #pragma unroll
      for (int v = 0; v < 4; v++){
        float p = acc[2*j][v] + bb[v];
        float sp, sg; sp_sig(p, sp, sg);
        pr[v] = sp; tg[v] = sg * acc[2*j+1][v];
      }
      *(float4*)&A[2*j  ][c0] = make_float4(pr[0],pr[1],pr[2],pr[3]);
      *(float4*)&A[2*j+1][c0] = make_float4(tg[0],tg[1],tg[2],tg[3]);
    }
  } else {
    #pragma unroll
    for (int r = 0; r < R; r++){
      float o[4];
      #pragma unroll
      for (int v = 0; v < 4; v++) o[v] = softplusf_(acc[r][v] + bb[v]);
      *(float4*)&A[r][c0] = make_float4(o[0],o[1],o[2],o[3]);
    }
  }
  __syncwarp();
}

// Per-warp L3: H[R][KV] = A[R][HV] @ W3 (+b3 for primal rows).
// 4 lanes per row, shfl-reduce. PAIRED: only even rows get b3.
template<int R, bool PAIRED>
__device__ __forceinline__ void l3_w(const float (* __restrict__ A)[HV],
                                     const float* __restrict__ W3,
                                     const float* __restrict__ b3,
                                     float (* __restrict__ H)[KV],
                                     int lane){
  const int r = lane >> 2, part = lane & 3;
  float hk[8];
  #pragma unroll
  for (int k = 0; k < 8; k++) hk[k] = 0.f;
  if (r < R){
    const int i0 = part * 32;
    #pragma unroll 4
    for (int i = i0; i < i0 + 32; i += 4){
      float4 a = *(const float4*)&A[r][i];
      float av[4] = {a.x, a.y, a.z, a.w};
      #pragma unroll
      for (int j = 0; j < 4; j++){
        float4 w0 = *(const float4*)&W3[(i+j)*KV];
        float4 w1 = *(const float4*)&W3[(i+j)*KV + 4];
        hk[0]=fmaf(av[j],w0.x,hk[0]); hk[1]=fmaf(av[j],w0.y,hk[1]);
        hk[2]=fmaf(av[j],w0.z,hk[2]); hk[3]=fmaf(av[j],w0.w,hk[3]);
        hk[4]=fmaf(av[j],w1.x,hk[4]); hk[5]=fmaf(av[j],w1.y,hk[5]);
        hk[6]=fmaf(av[j],w1.z,hk[6]); hk[7]=fmaf(av[j],w1.w,hk[7]);
      }
    }
  }
  #pragma unroll
  for (int k = 0; k < 8; k++){
    hk[k] += __shfl_xor_sync(FULLM, hk[k], 1);
    hk[k] += __shfl_xor_sync(FULLM, hk[k], 2);
  }
  if (part == 0 && r < R){
    const bool prim = PAIRED ? ((r & 1) == 0) : true;
    if (prim){
      #pragma unroll
      for (int k = 0; k < 8; k++) hk[k] += b3[k];
    }
    *(float4*)&H[r][0] = make_float4(hk[0],hk[1],hk[2],hk[3]);
    *(float4*)&H[r][4] = make_float4(hk[4],hk[5],hk[6],hk[7]);
  }
  __syncwarp();
}

__global__ void h0_kernel(const float* __restrict__ vW1, const float* __restrict__ vb1,
                          const float* __restrict__ vW2, const float* __restrict__ vb2,
                          const float* __restrict__ vW3, const float* __restrict__ vb3){
  __shared__ float h1[HV], h2[HV];
  int t = threadIdx.x;
  if (t < HV) h1[t] = softplusf_(vb1[t]);
  __syncthreads();
  if (t < HV){
    float acc = vb2[t];
    for (int i = 0; i < HV; i++) acc = fmaf(h1[i], vW2[i*HV + t], acc);
    h2[t] = softplusf_(acc);
  }
  __syncthreads();
  if (t < KV){
    float acc = vb3[t];
    for (int i = 0; i < HV; i++) acc = fmaf(h2[i], vW3[i*KV + t], acc);
    g_h0[t] = acc;
  }
}

__global__ void __launch_bounds__(THREADS, 1)
dyn_kernel(const float* __restrict__ x,
           const float* __restrict__ fW1, const float* __restrict__ fb1,
           const float* __restrict__ fW2, const float* __restrict__ fb2,
           const float* __restrict__ fW3, const float* __restrict__ fb3,
           const float* __restrict__ vW1, const float* __restrict__ vb1,
           const float* __restrict__ vW2, const float* __restrict__ vb2,
           const float* __restrict__ vW3, const float* __restrict__ vb3,
           float* __restrict__ out){
  extern __shared__ char smem_raw[];
  Smem& S = *reinterpret_cast<Smem*>(smem_raw);
  const int tid  = threadIdx.x;
  const int base = blockIdx.x * TB;

  // ================= block-cooperative phase (one time) =================
  for (int i = tid; i < NDIM*HV; i += THREADS) S.W1v[i] = vW1[i];
  for (int i = tid; i < HV*HV;  i += THREADS) S.W2v[i] = vW2[i];
  for (int i = tid; i < HV*KV;  i += THREADS) S.W3v[i] = vW3[i];
  for (int i = tid; i < HV;     i += THREADS){ S.b1v[i] = vb1[i]; S.b2v[i] = vb2[i]; }
  if (tid < KV){ S.b3v[tid] = vb3[tid]; S.h0s[tid] = g_h0[tid]; }
  for (int i = tid; i < NDIM*HF; i += THREADS) S.W1f[i] = fW1[i];
  for (int i = tid; i < HF*HF;   i += THREADS) S.W2f[i] = fW2[i];
  for (int i = tid; i < HF*NDIM; i += THREADS) S.W3f[i] = fW3[i];
  if (tid < HF){ S.b1f[tid] = fb1[tid]; S.b2f[tid] = fb2[tid]; }
  if (tid < NDIM) S.b3f[tid] = fb3[tid];
  for (int e = tid; e < TB*NDIM; e += THREADS){
    int s = e >> 5, i = e & 31;
    S.X[s][i] = x[(size_t)(base + s)*NDIM + i];
  }
  __syncthreads();

  // fhat (32->25->25->32), h1/h2 in Aw flat scratch, F into Fw
  float* FL = &S.Aw[0][0][0];   // 16384 floats scratch
  for (int o = tid; o < TB*HF; o += THREADS){
    int s = o / HF, j = o - s*HF;
    float acc = S.b1f[j];
    #pragma unroll
    for (int i = 0; i < NDIM; i++) acc = fmaf(S.X[s][i], S.W1f[i*HF + j], acc);
    FL[s*HF + j] = softplusf_(acc);
  }
  __syncthreads();
  for (int o = tid; o < TB*HF; o += THREADS){
    int s = o / HF, j = o - s*HF;
    float acc = S.b2f[j];
    #pragma unroll
    for (int i = 0; i < HF; i++) acc = fmaf(FL[s*HF + i], S.W2f[i*HF + j], acc);
    FL[8192 + s*HF + j] = softplusf_(acc);
  }
  __syncthreads();
  for (int o = tid; o < TB*NDIM; o += THREADS){
    int s = o >> 5, j = o & 31;
    float acc = S.b3f[j];
    #pragma unroll
    for (int i = 0; i < HF; i++) acc = fmaf(FL[8192 + s*HF + i], S.W3f[i*NDIM + j], acc);
    S.Fw[s >> 2][s & 3][j] = acc;
  }
  __syncthreads();   // LAST block-wide barrier — warps independent after this

  // ================= warp-autonomous phase =================
  const int w    = tid >> 5;
  const int lane = tid & 31;
  const int c0   = lane * 4;
  float (* __restrict__ Awp)[HV] = S.Aw[w];
  float (* __restrict__ C1p)[HV] = S.C1w[w];
  float (* __restrict__ Hwp)[KV] = S.Hw[w];

  float4 b1q = *(const float4*)&S.b1v[c0];
  const float bb1[4] = {b1q.x, b1q.y, b1q.z, b1q.w};

  // cached norms (lanes 0..3: sample j = lane)
  float normX = 0.f, normF = 0.f;
  if (lane < 4){
    #pragma unroll
    for (int i = 0; i < NDIM; i += 4){
      float4 xv = *(const float4*)&S.X[w*4 + lane][i];
      float4 fv = *(const float4*)&S.Fw[w][lane][i];
      normX = fmaf(xv.x,xv.x,fmaf(xv.y,xv.y,fmaf(xv.z,xv.z,fmaf(xv.w,xv.w,normX))));
      normF = fmaf(fv.x,fv.x,fmaf(fv.y,fv.y,fmaf(fv.z,fv.z,fmaf(fv.w,fv.w,normF))));
    }
  }

  // ---- initial eval: rows 0..3 = x_j, rows 4..7 = F_j (all primal);
  //      raw F-row preacts cached as c1 ----
  {
    float acc[8][4];
    #pragma unroll
    for (int r = 0; r < 8; r++){ acc[r][0]=0.f; acc[r][1]=0.f; acc[r][2]=0.f; acc[r][3]=0.f; }
    #pragma unroll
    for (int k = 0; k < NDIM; k += 4){
      float4 w0 = *(const float4*)&S.W1v[(k+0)*HV + c0];
      float4 w1 = *(const float4*)&S.W1v[(k+1)*HV + c0];
      float4 w2 = *(const float4*)&S.W1v[(k+2)*HV + c0];
      float4 w3 = *(const float4*)&S.W1v[(k+3)*HV + c0];
      #pragma unroll
      for (int r = 0; r < 8; r++){
        const float* src = (r < 4) ? &S.X[w*4 + r][0] : &S.Fw[w][r-4][0];
        float4 a = *(const float4*)&src[k];
        acc[r][0]=fmaf(a.x,w0.x,fmaf(a.y,w1.x,fmaf(a.z,w2.x,fmaf(a.w,w3.x,acc[r][0]))));
        acc[r][1]=fmaf(a.x,w0.y,fmaf(a.y,w1.y,fmaf(a.z,w2.y,fmaf(a.w,w3.y,acc[r][1]))));
        acc[r][2]=fmaf(a.x,w0.z,fmaf(a.y,w1.z,fmaf(a.z,w2.z,fmaf(a.w,w3.z,acc[r][2]))));
        acc[r][3]=fmaf(a.x,w0.w,fmaf(a.y,w1.w,fmaf(a.z,w2.w,fmaf(a.w,w3.w,acc[r][3]))));
      }
    }
    #pragma unroll
    for (int r = 4; r < 8; r++)
      *(float4*)&C1p[r-4][c0] = make_float4(acc[r][0],acc[r][1],acc[r][2],acc[r][3]);
    #pragma unroll
    for (int r = 0; r < 8; r++){
      float o[4];
      #pragma unroll
      for (int v = 0; v < 4; v++) o[v] = softplusf_(acc[r][v] + bb1[v]);
      *(float4*)&Awp[r][c0] = make_float4(o[0],o[1],o[2],o[3]);
    }
    __syncwarp();
  }
  l2_gemm<8,false>(Awp, S.W2v, S.b2v, lane);
  l3_w<8,false>(Awp, S.W3v, S.b3v, Hwp, lane);

  // ---- per-sample state (lanes 0..3) ----
  float tg = 0.f, e1l = 0.f, e2l = 1.f, s1l = 0.f, s2l = 0.f, gml = 1.f;
  int mloc = 0, violloc = 0;
  if (lane < 4){
    float vx = EPSV * normX, vf = EPSV * normF;
    #pragma unroll
    for (int k = 0; k < KV; k++){
      float dx = Hwp[lane][k]     - S.h0s[k];
      float df = Hwp[4 + lane][k] - S.h0s[k];
      vx = fmaf(dx, dx, vx);
      vf = fmaf(df, df, vf);
    }
    tg = BETA * vx;
    float r0v = vf - tg;
    mloc = (r0v > 0.f) ? 1 : 0;
    violloc = mloc;
    s1l = signf_(-tg);
    s2l = signf_(r0v);
  }
  unsigned act = __ballot_sync(FULLM, mloc);

  // ---- Newton + bisection loop (per-warp, no block syncs) ----
  for (int it = 0; it < MAX_ITER_R && act; ++it){
    // build rows from cached c1: row 2j primal(gamma), row 2j+1 tangent
    #pragma unroll
    for (int j = 0; j < 4; j++){
      float g = __shfl_sync(FULLM, gml, j);
      float4 c = *(const float4*)&C1p[j][c0];
      float cv[4] = {c.x, c.y, c.z, c.w};
      float pr[4], tv[4];
      #pragma unroll
      for (int v = 0; v < 4; v++){
        float p = fmaf(g, cv[v], bb1[v]);
        float sp, sg; sp_sig(p, sp, sg);
        pr[v] = sp; tv[v] = sg * cv[v];
      }
      *(float4*)&Awp[2*j  ][c0] = make_float4(pr[0],pr[1],pr[2],pr[3]);
      *(float4*)&Awp[2*j+1][c0] = make_float4(tv[0],tv[1],tv[2],tv[3]);
    }
    __syncwarp();
    l2_gemm<8,true>(Awp, S.W2v, S.b2v, lane);
    l3_w<8,true>(Awp, S.W3v, S.b3v, Hwp, lane);

    int bis = 0;
    if (lane < 4 && mloc){
      float g = gml;
      float vg  = EPSV * g * g * normF;
      float dvg = 2.f * EPSV * g * normF;
      #pragma unroll
      for (int k = 0; k < KV; k++){
        float d = Hwp[2*lane][k] - S.h0s[k];
        vg  = fmaf(d, d, vg);
        dvg = fmaf(2.f*d, Hwp[2*lane+1][k], dvg);
      }
      float resid = vg - tg;
      if (it > 0 && fabsf(resid) <= TOLR){
        mloc = 0;
      } else {
        float gn = gml - resid / dvg;
        if (!(gn >= e1l && gn <= e2l)){   // out-of-bracket OR NaN
          gml = 0.5f * (e1l + e2l);
          bis = 1;
        } else {
          gml = gn;
        }
      }
    }
    if (__ballot_sync(FULLM, bis)){
      // primal-only eval at updated gammas (rows 0..3)
      #pragma unroll
      for (int j = 0; j < 4; j++){
        float g = __shfl_sync(FULLM, gml, j);
        float4 c = *(const float4*)&C1p[j][c0];
        float o[4] = {
          softplusf_(fmaf(g, c.x, bb1[0])),
          softplusf_(fmaf(g, c.y, bb1[1])),
          softplusf_(fmaf(g, c.z, bb1[2])),
          softplusf_(fmaf(g, c.w, bb1[3]))};
        *(float4*)&Awp[j][c0] = make_float4(o[0],o[1],o[2],o[3]);
      }
      __syncwarp();
      l2_gemm<4,false>(Awp, S.W2v, S.b2v, lane);
      l3_w<4,false>(Awp, S.W3v, S.b3v, Hwp, lane);
      if (lane < 4 && bis){
        float g = gml;
        float vg = EPSV * g * g * normF;
        #pragma unroll
        for (int k = 0; k < KV; k++){
          float d = Hwp[lane][k] - S.h0s[k];
          vg = fmaf(d, d, vg);
        }
        float sa = signf_(vg - tg);
        if (sa * s1l < 0.f){ e2l = gml; s2l = sa; }
        if (sa * s2l < 0.f){ e1l = gml; s1l = sa; }
      }
    }
    act = __ballot_sync(FULLM, mloc);
  }

  // ---- output (per warp: its 4 samples) ----
  #pragma unroll
  for (int j = 0; j < 4; j++){
    float g  = __shfl_sync(FULLM, gml, j);
    int   vi = __shfl_sync(FULLM, violloc, j);
    float f  = S.Fw[w][j][lane];
    out[(size_t)(base + w*4 + j)*NDIM + lane] = vi ? f * g : f;
  }
}

extern "C" void kernel_launch(void* const* d_in, const int* in_sizes, int n_in,
                              void* d_out, int out_size){
  const float* x   = (const float*)d_in[0];
  const float* fW1 = (const float*)d_in[1];
  const float* fb1 = (const float*)d_in[2];
  const float* fW2 = (const float*)d_in[3];
  const float* fb2 = (const float*)d_in[4];
  const float* fW3 = (const float*)d_in[5];
  const float* fb3 = (const float*)d_in[6];
  const float* vW1 = (const float*)d_in[7];
  const float* vb1 = (const float*)d_in[8];
  const float* vW2 = (const float*)d_in[9];
  const float* vb2 = (const float*)d_in[10];
  const float* vW3 = (const float*)d_in[11];
  const float* vb3 = (const float*)d_in[12];
  float* out = (float*)d_out;

  cudaFuncSetAttribute(dyn_kernel, cudaFuncAttributeMaxDynamicSharedMemorySize,
                       (int)sizeof(Smem));
  h0_kernel<<<1, 128>>>(vW1, vb1, vW2, vb2, vW3, vb3);
  dyn_kernel<<<BN / TB, THREADS, sizeof(Smem)>>>(
      x, fW1, fb1, fW2, fb2, fW3, fb3,
      vW1, vb1, vW2, vb2, vW3, vb3, out);
}

// round 6
// speedup vs baseline: 2.2443x; 1.2989x over previous
#include <cuda_runtime.h>
#include <math.h>

#define BN 65536
#define NDIM 32
#define HF 25
#define HV 128
#define KV 8
#define WARPS 16
#define THREADS 512
#define SPW 4
#define NITEMS (BN/SPW)
#define LDAP 132
#define BETA 0.99f
#define TOLR 1e-4f
#define EPSV 1e-3f
#define MAX_ITER_R 1000
#define FULLM 0xffffffffu

__device__ float g_h0[KV];
__device__ int   g_ctr;

__device__ __forceinline__ float softplusf_(float x){
  float e = __expf(-fabsf(x));
  return fmaxf(x, 0.f) + __logf(1.f + e);
}
__device__ __forceinline__ void sp_sig(float p, float& sp, float& sg){
  float e = __expf(-fabsf(p));
  float inv = 1.f / (1.f + e);
  sp = fmaxf(p, 0.f) + __logf(1.f + e);
  sg = (p >= 0.f) ? inv : (1.f - inv);
}
__device__ __forceinline__ float signf_(float v){
  return (v > 0.f) ? 1.f : ((v < 0.f) ? -1.f : 0.f);
}

struct __align__(16) Smem {
  alignas(16) float W1v[NDIM*HV];        // 16KB
  alignas(16) float W2v[HV*HV];          // 64KB
  alignas(16) float W3v[HV*KV];          // 4KB
  alignas(16) float Aw[WARPS][8][LDAP];  // 66KB padded activation scratch
  alignas(16) float C1w[WARPS][SPW][HV]; // 32KB cached F@W1v
  alignas(16) float Xw[WARPS][SPW][NDIM];// 8KB
  alignas(16) float Fw[WARPS][SPW][NDIM];// 8KB
  alignas(16) float Hw[WARPS][8][KV];    // 4KB
  alignas(16) float b1v[HV];
  alignas(16) float b2v[HV];
  alignas(16) float b3v[KV], h0s[KV];
  alignas(16) float W1f[NDIM*HF];
  alignas(16) float W2f[HF*HF];
  alignas(16) float W3f[HF*NDIM];
  float b1f[HF], b2f[HF], b3f[NDIM];
};

// Per-warp L2: A[R][HV] = act(A[R][HV] @ W2 + b2). Single-buffer (read all,
// syncwarp, write). PAIRED: rows (2j,2j+1) = (primal, tangent) share the exp.
template<int R, bool PAIRED>
__device__ __forceinline__ void l2_gemm(float (* __restrict__ A)[LDAP],
                                        const float* __restrict__ W2,
                                        const float* __restrict__ b2,
                                        int lane){
  const int c0 = lane * 4;
  float acc[R][4];
  #pragma unroll
  for (int r = 0; r < R; r++){ acc[r][0]=0.f; acc[r][1]=0.f; acc[r][2]=0.f; acc[r][3]=0.f; }
  #pragma unroll 2
  for (int k = 0; k < HV; k += 4){
    float4 w0 = *(const float4*)&W2[(k+0)*HV + c0];
    float4 w1 = *(const float4*)&W2[(k+1)*HV + c0];
    float4 w2 = *(const float4*)&W2[(k+2)*HV + c0];
    float4 w3 = *(const float4*)&W2[(k+3)*HV + c0];
    #pragma unroll
    for (int r = 0; r < R; r++){
      float4 a = *(const float4*)&A[r][k];
      acc[r][0]=fmaf(a.x,w0.x,fmaf(a.y,w1.x,fmaf(a.z,w2.x,fmaf(a.w,w3.x,acc[r][0]))));
      acc[r][1]=fmaf(a.x,w0.y,fmaf(a.y,w1.y,fmaf(a.z,w2.y,fmaf(a.w,w3.y,acc[r][1]))));
      acc[r][2]=fmaf(a.x,w0.z,fmaf(a.y,w1.z,fmaf(a.z,w2.z,fmaf(a.w,w3.z,acc[r][2]))));
      acc[r][3]=fmaf(a.x,w0.w,fmaf(a.y,w1.w,fmaf(a.z,w2.w,fmaf(a.w,w3.w,acc[r][3]))));
    }
  }
  __syncwarp();
  float4 bv = *(const float4*)&b2[c0];
  float bb[4] = {bv.x, bv.y, bv.z, bv.w};
  if (PAIRED){
    #pragma unroll
    for (int j = 0; j < R/2; j++){
      float pr[4], tg[4];
      #pragma unroll
      for (int v = 0; v < 4; v++){
        float p = acc[2*j][v] + bb[v];
        float sp, sg; sp_sig(p, sp, sg);
        pr[v] = sp; tg[v] = sg * acc[2*j+1][v];
      }
      *(float4*)&A[2*j  ][c0] = make_float4(pr[0],pr[1],pr[2],pr[3]);
      *(float4*)&A[2*j+1][c0] = make_float4(tg[0],tg[1],tg[2],tg[3]);
    }
  } else {
    #pragma unroll
    for (int r = 0; r < R; r++){
      float o[4];
      #pragma unroll
      for (int v = 0; v < 4; v++) o[v] = softplusf_(acc[r][v] + bb[v]);
      *(float4*)&A[r][c0] = make_float4(o[0],o[1],o[2],o[3]);
    }
  }
  __syncwarp();
}

// Per-warp L3: lane r (< R) computes the full row r: H[r][0..7] = A[r][:]@W3.
// Padded rows (LDAP=132) make the R concurrent row-reads conflict-free; the
// W3 reads are identical across lanes (broadcast). No shfl reduction needed.
template<int R, bool PAIRED>
__device__ __forceinline__ void l3_lane(const float (* __restrict__ A)[LDAP],
                                        const float* __restrict__ W3,
                                        const float* __restrict__ b3,
                                        float (* __restrict__ H)[KV],
                                        int lane){
  if (lane < R){
    float hk[8];
    #pragma unroll
    for (int k = 0; k < 8; k++) hk[k] = 0.f;
    #pragma unroll 4
    for (int i = 0; i < HV; i += 4){
      float4 a = *(const float4*)&A[lane][i];
      float av[4] = {a.x, a.y, a.z, a.w};
      #pragma unroll
      for (int j = 0; j < 4; j++){
        float4 w0 = *(const float4*)&W3[(i+j)*KV];
        float4 w1 = *(const float4*)&W3[(i+j)*KV + 4];
        hk[0]=fmaf(av[j],w0.x,hk[0]); hk[1]=fmaf(av[j],w0.y,hk[1]);
        hk[2]=fmaf(av[j],w0.z,hk[2]); hk[3]=fmaf(av[j],w0.w,hk[3]);
        hk[4]=fmaf(av[j],w1.x,hk[4]); hk[5]=fmaf(av[j],w1.y,hk[5]);
        hk[6]=fmaf(av[j],w1.z,hk[6]); hk[7]=fmaf(av[j],w1.w,hk[7]);
      }
    }
    const bool prim = PAIRED ? ((lane & 1) == 0) : true;
    if (prim){
      #pragma unroll
      for (int k = 0; k < 8; k++) hk[k] += b3[k];
    }
    *(float4*)&H[lane][0] = make_float4(hk[0],hk[1],hk[2],hk[3]);
    *(float4*)&H[lane][4] = make_float4(hk[4],hk[5],hk[6],hk[7]);
  }
  __syncwarp();
}

__global__ void h0_kernel(const float* __restrict__ vW1, const float* __restrict__ vb1,
                          const float* __restrict__ vW2, const float* __restrict__ vb2,
                          const float* __restrict__ vW3, const float* __restrict__ vb3){
  __shared__ float h1[HV], h2[HV];
  int t = threadIdx.x;
  if (t == 0) g_ctr = 0;
  if (t < HV) h1[t] = softplusf_(vb1[t]);
  __syncthreads();
  if (t < HV){
    float acc = vb2[t];
    for (int i = 0; i < HV; i++) acc = fmaf(h1[i], vW2[i*HV + t], acc);
    h2[t] = softplusf_(acc);
  }
  __syncthreads();
  if (t < KV){
    float acc = vb3[t];
    for (int i = 0; i < HV; i++) acc = fmaf(h2[i], vW3[i*KV + t], acc);
    g_h0[t] = acc;
  }
}

__global__ void __launch_bounds__(THREADS, 1)
dyn_kernel(const float* __restrict__ x,
           const float* __restrict__ fW1, const float* __restrict__ fb1,
           const float* __restrict__ fW2, const float* __restrict__ fb2,
           const float* __restrict__ fW3, const float* __restrict__ fb3,
           const float* __restrict__ vW1, const float* __restrict__ vb1,
           const float* __restrict__ vW2, const float* __restrict__ vb2,
           const float* __restrict__ vW3, const float* __restrict__ vb3,
           float* __restrict__ out){
  extern __shared__ char smem_raw[];
  Smem& S = *reinterpret_cast<Smem*>(smem_raw);
  const int tid  = threadIdx.x;

  // ---- one-time weight load ----
  for (int i = tid; i < NDIM*HV; i += THREADS) S.W1v[i] = vW1[i];
  for (int i = tid; i < HV*HV;  i += THREADS) S.W2v[i] = vW2[i];
  for (int i = tid; i < HV*KV;  i += THREADS) S.W3v[i] = vW3[i];
  for (int i = tid; i < HV;     i += THREADS){ S.b1v[i] = vb1[i]; S.b2v[i] = vb2[i]; }
  if (tid < KV){ S.b3v[tid] = vb3[tid]; S.h0s[tid] = g_h0[tid]; }
  for (int i = tid; i < NDIM*HF; i += THREADS) S.W1f[i] = fW1[i];
  for (int i = tid; i < HF*HF;   i += THREADS) S.W2f[i] = fW2[i];
  for (int i = tid; i < HF*NDIM; i += THREADS) S.W3f[i] = fW3[i];
  if (tid < HF){ S.b1f[tid] = fb1[tid]; S.b2f[tid] = fb2[tid]; }
  if (tid < NDIM) S.b3f[tid] = fb3[tid];
  __syncthreads();   // only block-wide barrier

  const int w    = tid >> 5;
  const int lane = tid & 31;
  const int c0   = lane * 4;
  float (* __restrict__ Awp)[LDAP] = S.Aw[w];
  float (* __restrict__ C1p)[HV]   = S.C1w[w];
  float (* __restrict__ Hwp)[KV]   = S.Hw[w];

  float4 b1q = *(const float4*)&S.b1v[c0];
  const float bb1[4] = {b1q.x, b1q.y, b1q.z, b1q.w};

  // ================= warp-autonomous persistent loop =================
  for (;;){
    int item;
    if (lane == 0) item = atomicAdd(&g_ctr, 1);
    item = __shfl_sync(FULLM, item, 0);
    if (item >= NITEMS) break;
    const size_t sbase = (size_t)item * SPW;

    // ---- load x (4 samples, 512B coalesced) ----
    ((float4*)&S.Xw[w][0][0])[lane] = ((const float4*)(x + sbase*NDIM))[lane];
    __syncwarp();

    // ---- fhat per warp: 32 -> 25 -> 25 -> 32 ----
    float* scr = &Awp[0][0];   // 1056-float scratch (overwritten later)
    if (lane < HF){
      #pragma unroll
      for (int s = 0; s < SPW; s++){
        float acc = S.b1f[lane];
        #pragma unroll
        for (int i = 0; i < NDIM; i++) acc = fmaf(S.Xw[w][s][i], S.W1f[i*HF + lane], acc);
        scr[s*HF + lane] = softplusf_(acc);
      }
    }
    __syncwarp();
    if (lane < HF){
      #pragma unroll
      for (int s = 0; s < SPW; s++){
        float acc = S.b2f[lane];
        #pragma unroll
        for (int i = 0; i < HF; i++) acc = fmaf(scr[s*HF + i], S.W2f[i*HF + lane], acc);
        scr[512 + s*HF + lane] = softplusf_(acc);
      }
    }
    __syncwarp();
    {
      #pragma unroll
      for (int s = 0; s < SPW; s++){
        float acc = S.b3f[lane];
        #pragma unroll
        for (int i = 0; i < HF; i++) acc = fmaf(scr[512 + s*HF + i], S.W3f[i*NDIM + lane], acc);
        S.Fw[w][s][lane] = acc;
      }
    }
    __syncwarp();

    // cached norms (lanes 0..3)
    float normX = 0.f, normF = 0.f;
    if (lane < SPW){
      #pragma unroll
      for (int i = 0; i < NDIM; i += 4){
        float4 xv = *(const float4*)&S.Xw[w][lane][i];
        float4 fv = *(const float4*)&S.Fw[w][lane][i];
        normX = fmaf(xv.x,xv.x,fmaf(xv.y,xv.y,fmaf(xv.z,xv.z,fmaf(xv.w,xv.w,normX))));
        normF = fmaf(fv.x,fv.x,fmaf(fv.y,fv.y,fmaf(fv.z,fv.z,fmaf(fv.w,fv.w,normF))));
      }
    }

    // ---- initial L1: rows 0..3 = x_s, rows 4..7 = F_s (all primal);
    //      raw F-row preacts cached as C1 ----
    {
      float acc[8][4];
      #pragma unroll
      for (int r = 0; r < 8; r++){ acc[r][0]=0.f; acc[r][1]=0.f; acc[r][2]=0.f; acc[r][3]=0.f; }
      #pragma unroll
      for (int k = 0; k < NDIM; k += 4){
        float4 w0 = *(const float4*)&S.W1v[(k+0)*HV + c0];
        float4 w1 = *(const float4*)&S.W1v[(k+1)*HV + c0];
        float4 w2 = *(const float4*)&S.W1v[(k+2)*HV + c0];
        float4 w3 = *(const float4*)&S.W1v[(k+3)*HV + c0];
        #pragma unroll
        for (int r = 0; r < 8; r++){
          const float* src = (r < 4) ? &S.Xw[w][r][0] : &S.Fw[w][r-4][0];
          float4 a = *(const float4*)&src[k];
          acc[r][0]=fmaf(a.x,w0.x,fmaf(a.y,w1.x,fmaf(a.z,w2.x,fmaf(a.w,w3.x,acc[r][0]))));
          acc[r][1]=fmaf(a.x,w0.y,fmaf(a.y,w1.y,fmaf(a.z,w2.y,fmaf(a.w,w3.y,acc[r][1]))));
          acc[r][2]=fmaf(a.x,w0.z,fmaf(a.y,w1.z,fmaf(a.z,w2.z,fmaf(a.w,w3.z,acc[r][2]))));
          acc[r][3]=fmaf(a.x,w0.w,fmaf(a.y,w1.w,fmaf(a.z,w2.w,fmaf(a.w,w3.w,acc[r][3]))));
        }
      }
      __syncwarp();   // scr reads (fhat) done before Aw overwrite
      #pragma unroll
      for (int r = 4; r < 8; r++)
        *(float4*)&C1p[r-4][c0] = make_float4(acc[r][0],acc[r][1],acc[r][2],acc[r][3]);
      #pragma unroll
      for (int r = 0; r < 8; r++){
        float o[4];
        #pragma unroll
        for (int v = 0; v < 4; v++) o[v] = softplusf_(acc[r][v] + bb1[v]);
        *(float4*)&Awp[r][c0] = make_float4(o[0],o[1],o[2],o[3]);
      }
      __syncwarp();
    }
    l2_gemm<8,false>(Awp, S.W2v, S.b2v, lane);
    l3_lane<8,false>(Awp, S.W3v, S.b3v, Hwp, lane);

    // ---- per-sample state (lanes 0..3) ----
    float tg = 0.f, e1l = 0.f, e2l = 1.f, s1l = 0.f, s2l = 0.f, gml = 1.f;
    int mloc = 0, violloc = 0;
    if (lane < SPW){
      float vx = EPSV * normX, vf = EPSV * normF;
      #pragma unroll
      for (int k = 0; k < KV; k++){
        float dx = Hwp[lane][k]     - S.h0s[k];
        float df = Hwp[4 + lane][k] - S.h0s[k];
        vx = fmaf(dx, dx, vx);
        vf = fmaf(df, df, vf);
      }
      tg = BETA * vx;
      float r0v = vf - tg;
      mloc = (r0v > 0.f) ? 1 : 0;
      violloc = mloc;
      s1l = signf_(-tg);
      s2l = signf_(r0v);
    }
    unsigned act = __ballot_sync(FULLM, mloc);

    // ---- Newton + bisection (per-warp, no block syncs) ----
    for (int it = 0; it < MAX_ITER_R && act; ++it){
      #pragma unroll
      for (int j = 0; j < SPW; j++){
        float g = __shfl_sync(FULLM, gml, j);
        float4 c = *(const float4*)&C1p[j][c0];
        float cv[4] = {c.x, c.y, c.z, c.w};
        float pr[4], tv[4];
        #pragma unroll
        for (int v = 0; v < 4; v++){
          float p = fmaf(g, cv[v], bb1[v]);
          float sp, sg; sp_sig(p, sp, sg);
          pr[v] = sp; tv[v] = sg * cv[v];
        }
        *(float4*)&Awp[2*j  ][c0] = make_float4(pr[0],pr[1],pr[2],pr[3]);
        *(float4*)&Awp[2*j+1][c0] = make_float4(tv[0],tv[1],tv[2],tv[3]);
      }
      __syncwarp();
      l2_gemm<8,true>(Awp, S.W2v, S.b2v, lane);
      l3_lane<8,true>(Awp, S.W3v, S.b3v, Hwp, lane);

      int bis = 0;
      if (lane < SPW && mloc){
        float g = gml;
        float vg  = EPSV * g * g * normF;
        float dvg = 2.f * EPSV * g * normF;
        #pragma unroll
        for (int k = 0; k < KV; k++){
          float d = Hwp[2*lane][k] - S.h0s[k];
          vg  = fmaf(d, d, vg);
          dvg = fmaf(2.f*d, Hwp[2*lane+1][k], dvg);
        }
        float resid = vg - tg;
        if (it > 0 && fabsf(resid) <= TOLR){
          mloc = 0;
        } else {
          float gn = gml - resid / dvg;
          if (!(gn >= e1l && gn <= e2l)){   // out-of-bracket OR NaN
            gml = 0.5f * (e1l + e2l);
            bis = 1;
          } else {
            gml = gn;
          }
        }
      }
      if (__ballot_sync(FULLM, bis)){
        // primal-only eval at updated gammas (rows 0..3)
        #pragma unroll
        for (int j = 0; j < SPW; j++){
          float g = __shfl_sync(FULLM, gml, j);
          float4 c = *(const float4*)&C1p[j][c0];
          float o[4] = {
            softplusf_(fmaf(g, c.x, bb1[0])),
            softplusf_(fmaf(g, c.y, bb1[1])),
            softplusf_(fmaf(g, c.z, bb1[2])),
            softplusf_(fmaf(g, c.w, bb1[3]))};
          *(float4*)&Awp[j][c0] = make_float4(o[0],o[1],o[2],o[3]);
        }
        __syncwarp();
        l2_gemm<4,false>(Awp, S.W2v, S.b2v, lane);
        l3_lane<4,false>(Awp, S.W3v, S.b3v, Hwp, lane);
        if (lane < SPW && bis){
          float g = gml;
          float vg = EPSV * g * g * normF;
          #pragma unroll
          for (int k = 0; k < KV; k++){
            float d = Hwp[lane][k] - S.h0s[k];
            vg = fmaf(d, d, vg);
          }
          float sa = signf_(vg - tg);
          if (sa * s1l < 0.f){ e2l = gml; s2l = sa; }
          if (sa * s2l < 0.f){ e1l = gml; s1l = sa; }
        }
      }
      act = __ballot_sync(FULLM, mloc);
    }

    // ---- output (4 samples, coalesced) ----
    #pragma unroll
    for (int j = 0; j < SPW; j++){
      float g  = __shfl_sync(FULLM, gml, j);
      int   vi = __shfl_sync(FULLM, violloc, j);
      float f  = S.Fw[w][j][lane];
      out[(sbase + j)*NDIM + lane] = vi ? f * g : f;
    }
  }
}

extern "C" void kernel_launch(void* const* d_in, const int* in_sizes, int n_in,
                              void* d_out, int out_size){
  const float* x   = (const float*)d_in[0];
  const float* fW1 = (const float*)d_in[1];
  const float* fb1 = (const float*)d_in[2];
  const float* fW2 = (const float*)d_in[3];
  const float* fb2 = (const float*)d_in[4];
  const float* fW3 = (const float*)d_in[5];
  const float* fb3 = (const float*)d_in[6];
  const float* vW1 = (const float*)d_in[7];
  const float* vb1 = (const float*)d_in[8];
  const float* vW2 = (const float*)d_in[9];
  const float* vb2 = (const float*)d_in[10];
  const float* vW3 = (const float*)d_in[11];
  const float* vb3 = (const float*)d_in[12];
  float* out = (float*)d_out;

  int dev = 0;
  cudaGetDevice(&dev);
  int sms = 148;
  cudaDeviceGetAttribute(&sms, cudaDevAttrMultiProcessorCount, dev);

  cudaFuncSetAttribute(dyn_kernel, cudaFuncAttributeMaxDynamicSharedMemorySize,
                       (int)sizeof(Smem));
  h0_kernel<<<1, 128>>>(vW1, vb1, vW2, vb2, vW3, vb3);
  dyn_kernel<<<sms, THREADS, sizeof(Smem)>>>(
      x, fW1, fb1, fW2, fb2, fW3, fb3,
      vW1, vb1, vW2, vb2, vW3, vb3, out);
}

// round 7
// speedup vs baseline: 3.2502x; 1.4482x over previous
#include <cuda_runtime.h>
#include <math.h>

#define BN 65536
#define NDIM 32
#define HF 25
#define HV 128
#define KV 8
#define WARPS 16
#define THREADS 512
#define SPW 4
#define NITEMS (BN/SPW)
#define LDAP 132
#define LDW3 132
#define BETA 0.99f
#define TOLR 1e-4f
#define EPSV 1e-3f
#define MAX_ITER_R 1000
#define FULLM 0xffffffffu

__device__ float g_h0[KV];
__device__ int   g_ctr;

__device__ __forceinline__ float softplusf_(float x){
  float e = __expf(-fabsf(x));
  return fmaxf(x, 0.f) + __logf(1.f + e);
}
__device__ __forceinline__ void sp_sig(float p, float& sp, float& sg){
  float e = __expf(-fabsf(p));
  float inv = 1.f / (1.f + e);
  sp = fmaxf(p, 0.f) + __logf(1.f + e);
  sg = (p >= 0.f) ? inv : (1.f - inv);
}
__device__ __forceinline__ float signf_(float v){
  return (v > 0.f) ? 1.f : ((v < 0.f) ? -1.f : 0.f);
}

struct __align__(16) Smem {
  alignas(16) float W1v[NDIM*HV];        // 16KB
  alignas(16) float W2v[HV*HV];          // 64KB
  alignas(16) float W3T[KV*LDW3];        // 4.2KB transposed W3 (row stride 132)
  alignas(16) float Aw[WARPS][8][LDAP];  // 66KB padded activation scratch
  alignas(16) float C1w[WARPS][SPW][HV]; // 32KB cached F@W1v
  alignas(16) float Xw[WARPS][SPW][NDIM];// 8KB
  alignas(16) float Fw[WARPS][SPW][NDIM];// 8KB
  alignas(16) float Hw[WARPS][8][KV];    // 4KB
  alignas(16) float b1v[HV];
  alignas(16) float b2v[HV];
  alignas(16) float b3v[KV], h0s[KV];
  alignas(16) float W1f[NDIM*HF];
  alignas(16) float W2f[HF*HF];
  alignas(16) float W3f[HF*NDIM];
  float b1f[HF], b2f[HF], b3f[NDIM];
};

// Per-warp L2: A[R][HV] = act(A[R][HV] @ W2 + b2). Single-buffer (read all,
// syncwarp, write). PAIRED: rows (2j,2j+1) = (primal, tangent) share the exp.
template<int R, bool PAIRED>
__device__ __forceinline__ void l2_gemm(float (* __restrict__ A)[LDAP],
                                        const float* __restrict__ W2,
                                        const float* __restrict__ b2,
                                        int lane){
  const int c0 = lane * 4;
  float acc[R][4];
  #pragma unroll
  for (int r = 0; r < R; r++){ acc[r][0]=0.f; acc[r][1]=0.f; acc[r][2]=0.f; acc[r][3]=0.f; }
  #pragma unroll 2
  for (int k = 0; k < HV; k += 4){
    float4 w0 = *(const float4*)&W2[(k+0)*HV + c0];
    float4 w1 = *(const float4*)&W2[(k+1)*HV + c0];
    float4 w2 = *(const float4*)&W2[(k+2)*HV + c0];
    float4 w3 = *(const float4*)&W2[(k+3)*HV + c0];
    #pragma unroll
    for (int r = 0; r < R; r++){
      float4 a = *(const float4*)&A[r][k];
      acc[r][0]=fmaf(a.x,w0.x,fmaf(a.y,w1.x,fmaf(a.z,w2.x,fmaf(a.w,w3.x,acc[r][0]))));
      acc[r][1]=fmaf(a.x,w0.y,fmaf(a.y,w1.y,fmaf(a.z,w2.y,fmaf(a.w,w3.y,acc[r][1]))));
      acc[r][2]=fmaf(a.x,w0.z,fmaf(a.y,w1.z,fmaf(a.z,w2.z,fmaf(a.w,w3.z,acc[r][2]))));
      acc[r][3]=fmaf(a.x,w0.w,fmaf(a.y,w1.w,fmaf(a.z,w2.w,fmaf(a.w,w3.w,acc[r][3]))));
    }
  }
  __syncwarp();
  float4 bv = *(const float4*)&b2[c0];
  float bb[4] = {bv.x, bv.y, bv.z, bv.w};
  if (PAIRED){
    #pragma unroll
    for (int j = 0; j < R/2; j++){
      float pr[4], tg[4];
      #pragma unroll
      for (int v = 0; v < 4; v++){
        float p = acc[2*j][v] + bb[v];
        float sp, sg; sp_sig(p, sp, sg);
        pr[v] = sp; tg[v] = sg * acc[2*j+1][v];
      }
      *(float4*)&A[2*j  ][c0] = make_float4(pr[0],pr[1],pr[2],pr[3]);
      *(float4*)&A[2*j+1][c0] = make_float4(tg[0],tg[1],tg[2],tg[3]);
    }
  } else {
    #pragma unroll
    for (int r = 0; r < R; r++){
      float o[4];
      #pragma unroll
      for (int v = 0; v < 4; v++) o[v] = softplusf_(acc[r][v] + bb[v]);
      *(float4*)&A[r][c0] = make_float4(o[0],o[1],o[2],o[3]);
    }
  }
  __syncwarp();
}

// Per-warp L3, all 32 lanes: lane -> (row rr = lane>>2, col pair cp=(lane&3)*2).
// Full-k accumulation per lane, no reduction. Conflict-free:
//   A[rr][i]       : 8 rows, bank offset 4*rr (distinct mod 32), 4-lane broadcast
//   W3T[cp..cp+1]  : 8 rows, bank offset 4*c  (distinct mod 32), 4-lane broadcast
// allprim: all rows get b3; else only even rows (paired primal/tangent).
__device__ __forceinline__ void l3_lane(const float (* __restrict__ A)[LDAP],
                                        const float* __restrict__ W3T,
                                        const float* __restrict__ b3,
                                        float (* __restrict__ H)[KV],
                                        int lane, bool allprim){
  const int rr = lane >> 2;
  const int cp = (lane & 3) * 2;
  float h0 = 0.f, h1 = 0.f;
  #pragma unroll 4
  for (int i = 0; i < HV; i += 4){
    float4 a  = *(const float4*)&A[rr][i];
    float4 w0 = *(const float4*)&W3T[cp*LDW3 + i];
    float4 w1 = *(const float4*)&W3T[(cp+1)*LDW3 + i];
    h0 = fmaf(a.x,w0.x,fmaf(a.y,w0.y,fmaf(a.z,w0.z,fmaf(a.w,w0.w,h0))));
    h1 = fmaf(a.x,w1.x,fmaf(a.y,w1.y,fmaf(a.z,w1.z,fmaf(a.w,w1.w,h1))));
  }
  const bool prim = allprim || ((rr & 1) == 0);
  if (prim){ h0 += b3[cp]; h1 += b3[cp+1]; }
  H[rr][cp]   = h0;
  H[rr][cp+1] = h1;
  __syncwarp();
}

__global__ void h0_kernel(const float* __restrict__ vW1, const float* __restrict__ vb1,
                          const float* __restrict__ vW2, const float* __restrict__ vb2,
                          const float* __restrict__ vW3, const float* __restrict__ vb3){
  __shared__ float h1[HV], h2[HV];
  int t = threadIdx.x;
  if (t == 0) g_ctr = 0;
  if (t < HV) h1[t] = softplusf_(vb1[t]);
  __syncthreads();
  if (t < HV){
    float acc = vb2[t];
    for (int i = 0; i < HV; i++) acc = fmaf(h1[i], vW2[i*HV + t], acc);
    h2[t] = softplusf_(acc);
  }
  __syncthreads();
  if (t < KV){
    float acc = vb3[t];
    for (int i = 0; i < HV; i++) acc = fmaf(h2[i], vW3[i*KV + t], acc);
    g_h0[t] = acc;
  }
}

__global__ void __launch_bounds__(THREADS, 1)
dyn_kernel(const float* __restrict__ x,
           const float* __restrict__ fW1, const float* __restrict__ fb1,
           const float* __restrict__ fW2, const float* __restrict__ fb2,
           const float* __restrict__ fW3, const float* __restrict__ fb3,
           const float* __restrict__ vW1, const float* __restrict__ vb1,
           const float* __restrict__ vW2, const float* __restrict__ vb2,
           const float* __restrict__ vW3, const float* __restrict__ vb3,
           float* __restrict__ out){
  extern __shared__ char smem_raw[];
  Smem& S = *reinterpret_cast<Smem*>(smem_raw);
  const int tid  = threadIdx.x;

  // ---- one-time weight load ----
  for (int i = tid; i < NDIM*HV; i += THREADS) S.W1v[i] = vW1[i];
  for (int i = tid; i < HV*HV;  i += THREADS) S.W2v[i] = vW2[i];
  for (int i = tid; i < HV*KV;  i += THREADS){
    int k = i >> 3, c = i & 7;               // vW3 is [HV][KV]
    S.W3T[c*LDW3 + k] = vW3[i];
  }
  for (int i = tid; i < HV;     i += THREADS){ S.b1v[i] = vb1[i]; S.b2v[i] = vb2[i]; }
  if (tid < KV){ S.b3v[tid] = vb3[tid]; S.h0s[tid] = g_h0[tid]; }
  for (int i = tid; i < NDIM*HF; i += THREADS) S.W1f[i] = fW1[i];
  for (int i = tid; i < HF*HF;   i += THREADS) S.W2f[i] = fW2[i];
  for (int i = tid; i < HF*NDIM; i += THREADS) S.W3f[i] = fW3[i];
  if (tid < HF){ S.b1f[tid] = fb1[tid]; S.b2f[tid] = fb2[tid]; }
  if (tid < NDIM) S.b3f[tid] = fb3[tid];
  __syncthreads();   // only block-wide barrier

  const int w    = tid >> 5;
  const int lane = tid & 31;
  const int c0   = lane * 4;
  float (* __restrict__ Awp)[LDAP] = S.Aw[w];
  float (* __restrict__ C1p)[HV]   = S.C1w[w];
  float (* __restrict__ Hwp)[KV]   = S.Hw[w];

  float4 b1q = *(const float4*)&S.b1v[c0];
  const float bb1[4] = {b1q.x, b1q.y, b1q.z, b1q.w};

  // ================= warp-autonomous persistent loop =================
  for (;;){
    int item;
    if (lane == 0) item = atomicAdd(&g_ctr, 1);
    item = __shfl_sync(FULLM, item, 0);
    if (item >= NITEMS) break;
    const size_t sbase = (size_t)item * SPW;

    // ---- load x (4 samples, 512B coalesced) ----
    ((float4*)&S.Xw[w][0][0])[lane] = ((const float4*)(x + sbase*NDIM))[lane];
    __syncwarp();

    // ---- fhat per warp: 32 -> 25 -> 25 -> 32 ----
    float* scr = &Awp[0][0];   // 1056-float scratch (overwritten later)
    if (lane < HF){
      #pragma unroll
      for (int s = 0; s < SPW; s++){
        float acc = S.b1f[lane];
        #pragma unroll
        for (int i = 0; i < NDIM; i++) acc = fmaf(S.Xw[w][s][i], S.W1f[i*HF + lane], acc);
        scr[s*HF + lane] = softplusf_(acc);
      }
    }
    __syncwarp();
    if (lane < HF){
      #pragma unroll
      for (int s = 0; s < SPW; s++){
        float acc = S.b2f[lane];
        #pragma unroll
        for (int i = 0; i < HF; i++) acc = fmaf(scr[s*HF + i], S.W2f[i*HF + lane], acc);
        scr[512 + s*HF + lane] = softplusf_(acc);
      }
    }
    __syncwarp();
    {
      #pragma unroll
      for (int s = 0; s < SPW; s++){
        float acc = S.b3f[lane];
        #pragma unroll
        for (int i = 0; i < HF; i++) acc = fmaf(scr[512 + s*HF + i], S.W3f[i*NDIM + lane], acc);
        S.Fw[w][s][lane] = acc;
      }
    }
    __syncwarp();

    // cached norms (lanes 0..3)
    float normX = 0.f, normF = 0.f;
    if (lane < SPW){
      #pragma unroll
      for (int i = 0; i < NDIM; i += 4){
        float4 xv = *(const float4*)&S.Xw[w][lane][i];
        float4 fv = *(const float4*)&S.Fw[w][lane][i];
        normX = fmaf(xv.x,xv.x,fmaf(xv.y,xv.y,fmaf(xv.z,xv.z,fmaf(xv.w,xv.w,normX))));
        normF = fmaf(fv.x,fv.x,fmaf(fv.y,fv.y,fmaf(fv.z,fv.z,fmaf(fv.w,fv.w,normF))));
      }
    }

    // ---- initial L1: rows 0..3 = x_s, rows 4..7 = F_s (all primal);
    //      raw F-row preacts cached as C1 ----
    {
      float acc[8][4];
      #pragma unroll
      for (int r = 0; r < 8; r++){ acc[r][0]=0.f; acc[r][1]=0.f; acc[r][2]=0.f; acc[r][3]=0.f; }
      #pragma unroll
      for (int k = 0; k < NDIM; k += 4){
        float4 w0 = *(const float4*)&S.W1v[(k+0)*HV + c0];
        float4 w1 = *(const float4*)&S.W1v[(k+1)*HV + c0];
        float4 w2 = *(const float4*)&S.W1v[(k+2)*HV + c0];
        float4 w3 = *(const float4*)&S.W1v[(k+3)*HV + c0];
        #pragma unroll
        for (int r = 0; r < 8; r++){
          const float* src = (r < 4) ? &S.Xw[w][r][0] : &S.Fw[w][r-4][0];
          float4 a = *(const float4*)&src[k];
          acc[r][0]=fmaf(a.x,w0.x,fmaf(a.y,w1.x,fmaf(a.z,w2.x,fmaf(a.w,w3.x,acc[r][0]))));
          acc[r][1]=fmaf(a.x,w0.y,fmaf(a.y,w1.y,fmaf(a.z,w2.y,fmaf(a.w,w3.y,acc[r][1]))));
          acc[r][2]=fmaf(a.x,w0.z,fmaf(a.y,w1.z,fmaf(a.z,w2.z,fmaf(a.w,w3.z,acc[r][2]))));
          acc[r][3]=fmaf(a.x,w0.w,fmaf(a.y,w1.w,fmaf(a.z,w2.w,fmaf(a.w,w3.w,acc[r][3]))));
        }
      }
      __syncwarp();   // fhat scratch reads done before Aw overwrite
      #pragma unroll
      for (int r = 4; r < 8; r++)
        *(float4*)&C1p[r-4][c0] = make_float4(acc[r][0],acc[r][1],acc[r][2],acc[r][3]);
      #pragma unroll
      for (int r = 0; r < 8; r++){
        float o[4];
        #pragma unroll
        for (int v = 0; v < 4; v++) o[v] = softplusf_(acc[r][v] + bb1[v]);
        *(float4*)&Awp[r][c0] = make_float4(o[0],o[1],o[2],o[3]);
      }
      __syncwarp();
    }
    l2_gemm<8,false>(Awp, S.W2v, S.b2v, lane);
    l3_lane(Awp, S.W3T, S.b3v, Hwp, lane, true);

    // ---- per-sample state (lanes 0..3) ----
    float tg = 0.f, e1l = 0.f, e2l = 1.f, s1l = 0.f, s2l = 0.f, gml = 1.f;
    int mloc = 0, violloc = 0;
    if (lane < SPW){
      float vx = EPSV * normX, vf = EPSV * normF;
      #pragma unroll
      for (int k = 0; k < KV; k++){
        float dx = Hwp[lane][k]     - S.h0s[k];
        float df = Hwp[4 + lane][k] - S.h0s[k];
        vx = fmaf(dx, dx, vx);
        vf = fmaf(df, df, vf);
      }
      tg = BETA * vx;
      float r0v = vf - tg;
      mloc = (r0v > 0.f) ? 1 : 0;
      violloc = mloc;
      s1l = signf_(-tg);
      s2l = signf_(r0v);
    }
    unsigned act = __ballot_sync(FULLM, mloc);

    // ---- Newton + bisection (per-warp, compacted to active slots) ----
    for (int it = 0; it < MAX_ITER_R && act; ++it){
      const unsigned amask = act & 0xFu;
      const int n = __popc((int)amask);
      #pragma unroll
      for (int j = 0; j < SPW; j++){
        if ((amask >> j) & 1u){   // uniform branch (amask is warp-uniform)
          int t = __popc((int)(amask & ((1u << j) - 1u)));
          float g = __shfl_sync(FULLM, gml, j);
          float4 c = *(const float4*)&C1p[j][c0];
          float cv[4] = {c.x, c.y, c.z, c.w};
          float pr[4], tv[4];
          #pragma unroll
          for (int v = 0; v < 4; v++){
            float p = fmaf(g, cv[v], bb1[v]);
            float sp, sg; sp_sig(p, sp, sg);
            pr[v] = sp; tv[v] = sg * cv[v];
          }
          *(float4*)&Awp[2*t  ][c0] = make_float4(pr[0],pr[1],pr[2],pr[3]);
          *(float4*)&Awp[2*t+1][c0] = make_float4(tv[0],tv[1],tv[2],tv[3]);
        }
      }
      __syncwarp();
      if (n <= 2) l2_gemm<4,true>(Awp, S.W2v, S.b2v, lane);
      else        l2_gemm<8,true>(Awp, S.W2v, S.b2v, lane);
      l3_lane(Awp, S.W3T, S.b3v, Hwp, lane, false);

      int bis = 0;
      if (lane < SPW && mloc){
        int t = __popc((int)(amask & ((1u << lane) - 1u)));
        float g = gml;
        float vg  = EPSV * g * g * normF;
        float dvg = 2.f * EPSV * g * normF;
        #pragma unroll
        for (int k = 0; k < KV; k++){
          float d = Hwp[2*t][k] - S.h0s[k];
          vg  = fmaf(d, d, vg);
          dvg = fmaf(2.f*d, Hwp[2*t+1][k], dvg);
        }
        float resid = vg - tg;
        if (it > 0 && fabsf(resid) <= TOLR){
          mloc = 0;
        } else {
          float gn = gml - resid / dvg;
          if (!(gn >= e1l && gn <= e2l)){   // out-of-bracket OR NaN
            gml = 0.5f * (e1l + e2l);
            bis = 1;
          } else {
            gml = gn;
          }
        }
      }
      const unsigned bmask = __ballot_sync(FULLM, bis) & 0xFu;
      if (bmask){
        // primal-only eval at bisection midpoints, compacted
        #pragma unroll
        for (int j = 0; j < SPW; j++){
          if ((bmask >> j) & 1u){
            int t = __popc((int)(bmask & ((1u << j) - 1u)));
            float g = __shfl_sync(FULLM, gml, j);
            float4 c = *(const float4*)&C1p[j][c0];
            float o[4] = {
              softplusf_(fmaf(g, c.x, bb1[0])),
              softplusf_(fmaf(g, c.y, bb1[1])),
              softplusf_(fmaf(g, c.z, bb1[2])),
              softplusf_(fmaf(g, c.w, bb1[3]))};
            *(float4*)&Awp[t][c0] = make_float4(o[0],o[1],o[2],o[3]);
          }
        }
        __syncwarp();
        l2_gemm<4,false>(Awp, S.W2v, S.b2v, lane);
        l3_lane(Awp, S.W3T, S.b3v, Hwp, lane, true);
        if (lane < SPW && bis){
          int t = __popc((int)(bmask & ((1u << lane) - 1u)));
          float g = gml;
          float vg = EPSV * g * g * normF;
          #pragma unroll
          for (int k = 0; k < KV; k++){
            float d = Hwp[t][k] - S.h0s[k];
            vg = fmaf(d, d, vg);
          }
          float sa = signf_(vg - tg);
          if (sa * s1l < 0.f){ e2l = gml; s2l = sa; }
          if (sa * s2l < 0.f){ e1l = gml; s1l = sa; }
        }
      }
      act = __ballot_sync(FULLM, mloc);
    }

    // ---- output (4 samples, coalesced) ----
    #pragma unroll
    for (int j = 0; j < SPW; j++){
      float g  = __shfl_sync(FULLM, gml, j);
      int   vi = __shfl_sync(FULLM, violloc, j);
      float f  = S.Fw[w][j][lane];
      out[(sbase + j)*NDIM + lane] = vi ? f * g : f;
    }
  }
}

extern "C" void kernel_launch(void* const* d_in, const int* in_sizes, int n_in,
                              void* d_out, int out_size){
  const float* x   = (const float*)d_in[0];
  const float* fW1 = (const float*)d_in[1];
  const float* fb1 = (const float*)d_in[2];
  const float* fW2 = (const float*)d_in[3];
  const float* fb2 = (const float*)d_in[4];
  const float* fW3 = (const float*)d_in[5];
  const float* fb3 = (const float*)d_in[6];
  const float* vW1 = (const float*)d_in[7];
  const float* vb1 = (const float*)d_in[8];
  const float* vW2 = (const float*)d_in[9];
  const float* vb2 = (const float*)d_in[10];
  const float* vW3 = (const float*)d_in[11];
  const float* vb3 = (const float*)d_in[12];
  float* out = (float*)d_out;

  int dev = 0;
  cudaGetDevice(&dev);
  int sms = 148;
  cudaDeviceGetAttribute(&sms, cudaDevAttrMultiProcessorCount, dev);

  cudaFuncSetAttribute(dyn_kernel, cudaFuncAttributeMaxDynamicSharedMemorySize,
                       (int)sizeof(Smem));
  h0_kernel<<<1, 128>>>(vW1, vb1, vW2, vb2, vW3, vb3);
  dyn_kernel<<<sms, THREADS, sizeof(Smem)>>>(
      x, fW1, fb1, fW2, fb2, fW3, fb3,
      vW1, vb1, vW2, vb2, vW3, vb3, out);
}